// round 13
// baseline (speedup 1.0000x reference)
#include <cuda_runtime.h>
#include <cuda_fp16.h>
#include <mma.h>
#include <math.h>

using namespace nvcuda;

#define NN 50000
#define NNP 50048            // padded rows (= 391 * 128) for unguarded tiles
#define NE 800000
#define IN_DIM 128
#define HID 32
#define HEADS 8
#define F1DIM 256
#define ODIM 64
#define NEG 0.2f
#define FULL 0xffffffffu

// ---------------- scratch (device globals; no allocation) ----------------
__device__ alignas(16) __half g_f1h[(size_t)NN  * F1DIM];  // fp16 gather table, layer 1
__device__ alignas(16) float  g_h  [(size_t)NNP * F1DIM];  // agg1 out; pad rows stay 0 forever
__device__ alignas(16) __half g_f2h[(size_t)NN  * ODIM];   // fp16 gather table, layer 2
__device__ float g_el1[NN * HEADS];
__device__ float g_er1[NN * HEADS];
__device__ float g_el2[NN];
__device__ float g_er2[NN];
__device__ int g_cnt [NN];
__device__ int g_off [NN + 1];
__device__ int g_pos [NN];
__device__ int g_psrc[NE];

__device__ __forceinline__ float lrelu(float x) { return x >= 0.f ? x : NEG * x; }
__device__ __forceinline__ float4 tf32_f4(float4 v) {
    v.x = wmma::__float_to_tf32(v.x); v.y = wmma::__float_to_tf32(v.y);
    v.z = wmma::__float_to_tf32(v.z); v.w = wmma::__float_to_tf32(v.w);
    return v;
}

// ---------------- CSR build ----------------
__global__ void zero_cnt() {
    int i = blockIdx.x * blockDim.x + threadIdx.x;
    if (i < NN) g_cnt[i] = 0;
}
__global__ void count_dst(const int* __restrict__ dst) {
    int e = blockIdx.x * blockDim.x + threadIdx.x;
    if (e < NE) atomicAdd(&g_cnt[dst[e]], 1);
}
__global__ void scan_off() {
    __shared__ int wsum[32];
    const int t = threadIdx.x;
    const int C = (NN + 1023) / 1024;
    const int base = t * C;
    int s = 0;
    for (int j = 0; j < C; j++) { int idx = base + j; if (idx < NN) s += g_cnt[idx]; }
    int lane = t & 31, wid = t >> 5;
    int v = s;
#pragma unroll
    for (int o = 1; o < 32; o <<= 1) { int n = __shfl_up_sync(FULL, v, o); if (lane >= o) v += n; }
    if (lane == 31) wsum[wid] = v;
    __syncthreads();
    if (wid == 0) {
        int w = wsum[lane];
#pragma unroll
        for (int o = 1; o < 32; o <<= 1) { int n = __shfl_up_sync(FULL, w, o); if (lane >= o) w += n; }
        wsum[lane] = w;
    }
    __syncthreads();
    int run = (v - s) + (wid > 0 ? wsum[wid - 1] : 0);
    for (int j = 0; j < C; j++) {
        int idx = base + j;
        if (idx < NN) { g_off[idx] = run; g_pos[idx] = run; run += g_cnt[idx]; }
    }
    if (t == 1023) g_off[NN] = NE;
}
__global__ void place_edges(const int* __restrict__ src, const int* __restrict__ dst) {
    int e = blockIdx.x * blockDim.x + threadIdx.x;
    if (e >= NE) return;
    int slot = atomicAdd(&g_pos[dst[e]], 1);
    g_psrc[slot] = src[e];
}

// ---------------- tf32 GEMM with fused attention epilogue ----------------
// BN=128 (layer 1) or 64 (layer 2). 8 warps: 4 in M x 2 in N; warp tile 32 x BN/2.
// tf32 conversion done once on the global->smem path (identical numerics).
// Epilogue stages C through smem (64-row passes for BN=128) and emits el/er + fp16 table.
#define LDA 40
template<int BN, bool ELUA, int EPI>
__global__ void __launch_bounds__(256, BN == 64 ? 2 : 1)
gemm_fused(const float* __restrict__ A, const float* __restrict__ B,
           const float* __restrict__ av, const float* __restrict__ rv,
           int M, int K, int Nn) {
    constexpr int LDB = BN + 8;
    constexpr int LDC = BN + 4;
    constexpr int NFRAG = BN / 32;             // b-frags per warp
    constexpr int BL = BN / 32;                // float4 B-loads per thread
    constexpr int CROWS = (BN == 128) ? 64 : 128;  // C-stage rows per pass
    constexpr int NP = (BN == 128) ? 2 : 1;
    constexpr int SB1 = 128 * LDA + 32 * LDB;
    constexpr int SB2 = CROWS * LDC;
    constexpr int SBUF = SB1 > SB2 ? SB1 : SB2;

    __shared__ float sbuf[SBUF];
    float* As = sbuf;
    float* Bs = sbuf + 128 * LDA;
    const int tid = threadIdx.x;
    const int wid = tid >> 5;
    const int wm = (wid & 3) * 32;
    const int wn = (wid >> 2) * (BN / 2);
    const int rowBase = blockIdx.y * 128;
    const int colBase = blockIdx.x * BN;

    int aRow[4], aK[4];
#pragma unroll
    for (int l = 0; l < 4; l++) {
        int f = tid + l * 256;
        aRow[l] = f >> 3; aK[l] = (f & 7) * 4;
    }
    int bRow[BL], bCol[BL];
#pragma unroll
    for (int l = 0; l < BL; l++) {
        int f = tid + l * 256;
        bRow[l] = f / (BN / 4); bCol[l] = (f % (BN / 4)) * 4;
    }

    wmma::fragment<wmma::accumulator, 16, 16, 8, float> acc[2][NFRAG];
#pragma unroll
    for (int i = 0; i < 2; i++)
#pragma unroll
        for (int j = 0; j < NFRAG; j++) wmma::fill_fragment(acc[i][j], 0.f);

    float4 pa[4], pb[BL];
#pragma unroll
    for (int l = 0; l < 4; l++) {
        pa[l] = make_float4(0.f, 0.f, 0.f, 0.f);
        if (rowBase + aRow[l] < M) pa[l] = *(const float4*)&A[(size_t)(rowBase + aRow[l]) * K + aK[l]];
    }
#pragma unroll
    for (int l = 0; l < BL; l++)
        pb[l] = *(const float4*)&B[(size_t)bRow[l] * Nn + colBase + bCol[l]];

    for (int k0 = 0; k0 < K; k0 += 32) {
#pragma unroll
        for (int l = 0; l < 4; l++) {
            float4 sa = pa[l];
            if (ELUA) {
                sa.x = sa.x > 0.f ? sa.x : expm1f(sa.x);
                sa.y = sa.y > 0.f ? sa.y : expm1f(sa.y);
                sa.z = sa.z > 0.f ? sa.z : expm1f(sa.z);
                sa.w = sa.w > 0.f ? sa.w : expm1f(sa.w);
            }
            sa = tf32_f4(sa);
            float* p = &As[aRow[l] * LDA + aK[l]];
            p[0] = sa.x; p[1] = sa.y; p[2] = sa.z; p[3] = sa.w;
        }
#pragma unroll
        for (int l = 0; l < BL; l++) {
            float4 sb = tf32_f4(pb[l]);
            float* p = &Bs[bRow[l] * LDB + bCol[l]];
            p[0] = sb.x; p[1] = sb.y; p[2] = sb.z; p[3] = sb.w;
        }
        __syncthreads();

        if (k0 + 32 < K) {
#pragma unroll
            for (int l = 0; l < 4; l++)
                if (rowBase + aRow[l] < M)
                    pa[l] = *(const float4*)&A[(size_t)(rowBase + aRow[l]) * K + (k0 + 32) + aK[l]];
#pragma unroll
            for (int l = 0; l < BL; l++)
                pb[l] = *(const float4*)&B[(size_t)(k0 + 32 + bRow[l]) * Nn + colBase + bCol[l]];
        }

#pragma unroll
        for (int kk = 0; kk < 32; kk += 8) {
            wmma::fragment<wmma::matrix_a, 16, 16, 8, wmma::precision::tf32, wmma::row_major> af[2];
            wmma::fragment<wmma::matrix_b, 16, 16, 8, wmma::precision::tf32, wmma::row_major> bf[NFRAG];
#pragma unroll
            for (int i = 0; i < 2; i++)
                wmma::load_matrix_sync(af[i], &As[(wm + i * 16) * LDA + kk], LDA);
#pragma unroll
            for (int j = 0; j < NFRAG; j++)
                wmma::load_matrix_sync(bf[j], &Bs[kk * LDB + wn + j * 16], LDB);
#pragma unroll
            for (int i = 0; i < 2; i++)
#pragma unroll
                for (int j = 0; j < NFRAG; j++)
                    wmma::mma_sync(acc[i][j], af[i], bf[j], acc[i][j]);
        }
        __syncthreads();
    }

    // ---- epilogue: stage C in smem (NP passes), emit el/er + fp16 table ----
#pragma unroll
    for (int p = 0; p < NP; p++) {
        if (NP == 1 || ((wid & 3) >> 1) == p) {
            const int lm = (NP == 1) ? wm : (wm & 63);
#pragma unroll
            for (int i = 0; i < 2; i++)
#pragma unroll
                for (int j = 0; j < NFRAG; j++)
                    wmma::store_matrix_sync(&sbuf[(lm + i * 16) * LDC + wn + j * 16], acc[i][j],
                                            LDC, wmma::mem_row_major);
        }
        __syncthreads();

        if (EPI == 1) {
            // BN==128: thread -> (row = tid>>2 in this 64-row pass, chunk c = tid&3 = one head)
            const int rowl = tid >> 2;
            const int c = tid & 3;
            const int gr = rowBase + p * 64 + rowl;
            const float* crow = &sbuf[rowl * LDC + c * 32];
            const int head = (colBase >> 5) + c;
            const float* ap = av + head * HID;
            const float* rp = rv + head * HID;
            float el = 0.f, er = 0.f;
            unsigned w[16];
#pragma unroll
            for (int d = 0; d < 32; d += 2) {
                float c0 = crow[d], c1 = crow[d + 1];
                el += c0 * ap[d] + c1 * ap[d + 1];
                er += c0 * rp[d] + c1 * rp[d + 1];
                __half2 hh = __floats2half2_rn(c0, c1);
                w[d >> 1] = *(unsigned*)&hh;
            }
            if (gr < NN) {
                g_el1[gr * HEADS + head] = el;
                g_er1[gr * HEADS + head] = er;
                uint4* d4 = (uint4*)&g_f1h[(size_t)gr * F1DIM + colBase + c * 32];
                const uint4* s4 = (const uint4*)w;
                d4[0] = s4[0]; d4[1] = s4[1]; d4[2] = s4[2]; d4[3] = s4[3];
            }
        } else {
            // BN==64: thread -> (row = tid>>1, half = tid&1); 64-dim dot across 2 threads
            const int rowl = tid >> 1;
            const int half = tid & 1;
            const int gr = rowBase + rowl;
            const float* crow = &sbuf[rowl * LDC + half * 32];
            const float* ap = av + half * 32;
            const float* rp = rv + half * 32;
            float el = 0.f, er = 0.f;
            unsigned w[16];
#pragma unroll
            for (int d = 0; d < 32; d += 2) {
                float c0 = crow[d], c1 = crow[d + 1];
                el += c0 * ap[d] + c1 * ap[d + 1];
                er += c0 * rp[d] + c1 * rp[d + 1];
                __half2 hh = __floats2half2_rn(c0, c1);
                w[d >> 1] = *(unsigned*)&hh;
            }
            float elf = el + __shfl_xor_sync(FULL, el, 1);
            float erf = er + __shfl_xor_sync(FULL, er, 1);
            if (gr < NN) {
                if (half == 0) { g_el2[gr] = elf; g_er2[gr] = erf; }
                uint4* d4 = (uint4*)&g_f2h[(size_t)gr * ODIM + half * 32];
                const uint4* s4 = (const uint4*)w;
                d4[0] = s4[0]; d4[1] = s4[1]; d4[2] = s4[2]; d4[3] = s4[3];
            }
        }
        if (p + 1 < NP) __syncthreads();
    }
}

// ---------------- layer-1 aggregation: warp/node, single pass, fp16 gather, 4x unroll --
__global__ void __launch_bounds__(256)
agg1(const float* __restrict__ b1) {
    int warp = (blockIdx.x * blockDim.x + threadIdx.x) >> 5;
    if (warp >= NN) return;
    const int lane = threadIdx.x & 31;
    const int node = warp;
    const int h4 = lane >> 2;
    const int beg = g_off[node], end = g_off[node + 1];

    const float er = g_er1[node * HEADS + h4];

    float acc[8];
#pragma unroll
    for (int j = 0; j < 8; j++) acc[j] = 0.f;
    float ssum = 0.f;

    int i = beg;
    for (; i + 4 <= end; i += 4) {
        int s0 = g_psrc[i], s1 = g_psrc[i + 1], s2 = g_psrc[i + 2], s3 = g_psrc[i + 3];
        float a0 = __expf(lrelu(g_el1[s0 * HEADS + h4] + er));
        float a1 = __expf(lrelu(g_el1[s1 * HEADS + h4] + er));
        float a2 = __expf(lrelu(g_el1[s2 * HEADS + h4] + er));
        float a3 = __expf(lrelu(g_el1[s3 * HEADS + h4] + er));
        uint4 u0 = *(const uint4*)&g_f1h[(size_t)s0 * F1DIM + lane * 8];
        uint4 u1 = *(const uint4*)&g_f1h[(size_t)s1 * F1DIM + lane * 8];
        uint4 u2 = *(const uint4*)&g_f1h[(size_t)s2 * F1DIM + lane * 8];
        uint4 u3 = *(const uint4*)&g_f1h[(size_t)s3 * F1DIM + lane * 8];
        ssum += (a0 + a1) + (a2 + a3);
        const __half2* p0 = (const __half2*)&u0;
        const __half2* p1 = (const __half2*)&u1;
        const __half2* p2 = (const __half2*)&u2;
        const __half2* p3 = (const __half2*)&u3;
#pragma unroll
        for (int j = 0; j < 4; j++) {
            float2 f0 = __half22float2(p0[j]);
            float2 f1 = __half22float2(p1[j]);
            float2 f2 = __half22float2(p2[j]);
            float2 f3 = __half22float2(p3[j]);
            acc[2*j + 0] += (a0 * f0.x + a1 * f1.x) + (a2 * f2.x + a3 * f3.x);
            acc[2*j + 1] += (a0 * f0.y + a1 * f1.y) + (a2 * f2.y + a3 * f3.y);
        }
    }
    for (; i < end; i++) {
        int s0 = g_psrc[i];
        float a0 = __expf(lrelu(g_el1[s0 * HEADS + h4] + er));
        uint4 u0 = *(const uint4*)&g_f1h[(size_t)s0 * F1DIM + lane * 8];
        ssum += a0;
        const __half2* p0 = (const __half2*)&u0;
#pragma unroll
        for (int j = 0; j < 4; j++) {
            float2 f0 = __half22float2(p0[j]);
            acc[2*j + 0] += a0 * f0.x;
            acc[2*j + 1] += a0 * f0.y;
        }
    }

    const float inv = ssum > 0.f ? 1.f / ssum : 0.f;
    const float4* bp = (const float4*)&b1[lane * 8];
    float4 bb0 = bp[0], bb1 = bp[1];
    float4* op = (float4*)&g_h[(size_t)node * F1DIM + lane * 8];
    op[0] = make_float4(acc[0] * inv + bb0.x, acc[1] * inv + bb0.y,
                        acc[2] * inv + bb0.z, acc[3] * inv + bb0.w);
    op[1] = make_float4(acc[4] * inv + bb1.x, acc[5] * inv + bb1.y,
                        acc[6] * inv + bb1.z, acc[7] * inv + bb1.w);
}

// ---------------- layer-2 aggregation: warp/node, single pass, fp16 gather ----------
__global__ void __launch_bounds__(256)
agg2(float* __restrict__ out, const float* __restrict__ b2) {
    int warp = (blockIdx.x * blockDim.x + threadIdx.x) >> 5;
    if (warp >= NN) return;
    const int lane = threadIdx.x & 31;
    const int node = warp;
    const int beg = g_off[node], end = g_off[node + 1];

    const float er = g_er2[node];

    float a0 = 0.f, a1 = 0.f, ssum = 0.f;
    int i = beg;
    for (; i + 4 <= end; i += 4) {
        int s0 = g_psrc[i], s1 = g_psrc[i+1], s2 = g_psrc[i+2], s3 = g_psrc[i+3];
        float e0 = __expf(lrelu(g_el2[s0] + er));
        float e1 = __expf(lrelu(g_el2[s1] + er));
        float e2 = __expf(lrelu(g_el2[s2] + er));
        float e3 = __expf(lrelu(g_el2[s3] + er));
        float2 v0 = __half22float2(*(const __half2*)&g_f2h[(size_t)s0 * ODIM + lane * 2]);
        float2 v1 = __half22float2(*(const __half2*)&g_f2h[(size_t)s1 * ODIM + lane * 2]);
        float2 v2 = __half22float2(*(const __half2*)&g_f2h[(size_t)s2 * ODIM + lane * 2]);
        float2 v3 = __half22float2(*(const __half2*)&g_f2h[(size_t)s3 * ODIM + lane * 2]);
        ssum += (e0 + e1) + (e2 + e3);
        a0 += e0 * v0.x + e1 * v1.x + e2 * v2.x + e3 * v3.x;
        a1 += e0 * v0.y + e1 * v1.y + e2 * v2.y + e3 * v3.y;
    }
    for (; i < end; i++) {
        int s = g_psrc[i];
        float e0 = __expf(lrelu(g_el2[s] + er));
        float2 v = __half22float2(*(const __half2*)&g_f2h[(size_t)s * ODIM + lane * 2]);
        ssum += e0;
        a0 += e0 * v.x;
        a1 += e0 * v.y;
    }
    const float inv = ssum > 0.f ? 1.f / ssum : 0.f;
    float2 bb = *(const float2*)&b2[lane * 2];
    *(float2*)&out[(size_t)node * ODIM + lane * 2] = make_float2(a0 * inv + bb.x, a1 * inv + bb.y);
}

// ---------------- launch ----------------
extern "C" void kernel_launch(void* const* d_in, const int* in_sizes, int n_in,
                              void* d_out, int out_size) {
    const float* feat = (const float*)d_in[0];
    const int*   src  = (const int*)  d_in[1];
    const int*   dst  = (const int*)  d_in[2];
    const float* W1   = (const float*)d_in[3];
    const float* al1  = (const float*)d_in[4];
    const float* ar1  = (const float*)d_in[5];
    const float* b1   = (const float*)d_in[6];
    const float* W2   = (const float*)d_in[7];
    const float* al2  = (const float*)d_in[8];
    const float* ar2  = (const float*)d_in[9];
    const float* b2   = (const float*)d_in[10];
    float* out = (float*)d_out;

    float* ph;
    cudaGetSymbolAddress((void**)&ph, g_h);

    const int T = 256;
    auto cdiv = [](long long a, long long b) { return (int)((a + b - 1) / b); };

    // CSR build (shared by both layers)
    zero_cnt<<<cdiv(NN, T), T>>>();
    count_dst<<<cdiv(NE, T), T>>>(dst);
    scan_off<<<1, 1024>>>();
    place_edges<<<cdiv(NE, T), T>>>(src, dst);

    // Layer 1: f1h/el1/er1 = fused(feat @ W1), BN=128
    gemm_fused<128, false, 1><<<dim3(F1DIM / 128, NNP / 128), 256>>>(feat, W1, al1, ar1, NN, IN_DIM, F1DIM);
    agg1<<<cdiv((long long)NN * 32, T), T>>>(b1);

    // Layer 2: f2h/el2/er2 = fused(ELU(g_h) @ W2), BN=64; g_h pad rows stay 0 -> safe
    gemm_fused<64, true, 2><<<dim3(ODIM / 64, NNP / 128), 256>>>(ph, W2, al2, ar2, NNP, F1DIM, ODIM);
    agg2<<<cdiv((long long)NN * 32, T), T>>>(out, b2);
}

// round 14
// speedup vs baseline: 1.0507x; 1.0507x over previous
#include <cuda_runtime.h>
#include <cuda_fp16.h>
#include <mma.h>
#include <math.h>

using namespace nvcuda;

#define NN 50000
#define NNP 50048            // padded rows (= 391 * 128) for unguarded tiles
#define NE 800000
#define IN_DIM 128
#define HID 32
#define HEADS 8
#define F1DIM 256
#define ODIM 64
#define NEG 0.2f
#define FULL 0xffffffffu

// ---------------- scratch (device globals; no allocation) ----------------
__device__ alignas(16) __half g_f1h[(size_t)NN  * F1DIM];  // fp16 gather table, layer 1
__device__ alignas(16) float  g_h  [(size_t)NNP * F1DIM];  // agg1 out; pad rows stay 0 forever
__device__ alignas(16) __half g_f2h[(size_t)NN  * ODIM];   // fp16 gather table, layer 2
__device__ float g_el1[NN * HEADS];
__device__ float g_er1[NN * HEADS];
__device__ float g_el2[NN];
__device__ float g_er2[NN];
__device__ int g_cnt [NN];
__device__ int g_off [NN + 1];
__device__ int g_pos [NN];
__device__ int g_psrc[NE];

__device__ __forceinline__ float lrelu(float x) { return x >= 0.f ? x : NEG * x; }
__device__ __forceinline__ float4 tf32_f4(float4 v) {
    v.x = wmma::__float_to_tf32(v.x); v.y = wmma::__float_to_tf32(v.y);
    v.z = wmma::__float_to_tf32(v.z); v.w = wmma::__float_to_tf32(v.w);
    return v;
}

// ---------------- CSR build ----------------
__global__ void zero_cnt() {
    int i = blockIdx.x * blockDim.x + threadIdx.x;
    if (i < NN) g_cnt[i] = 0;
}
__global__ void count_dst(const int* __restrict__ dst) {
    int e = blockIdx.x * blockDim.x + threadIdx.x;
    if (e < NE) atomicAdd(&g_cnt[dst[e]], 1);
}
__global__ void scan_off() {
    __shared__ int wsum[32];
    const int t = threadIdx.x;
    const int C = (NN + 1023) / 1024;
    const int base = t * C;
    int s = 0;
    for (int j = 0; j < C; j++) { int idx = base + j; if (idx < NN) s += g_cnt[idx]; }
    int lane = t & 31, wid = t >> 5;
    int v = s;
#pragma unroll
    for (int o = 1; o < 32; o <<= 1) { int n = __shfl_up_sync(FULL, v, o); if (lane >= o) v += n; }
    if (lane == 31) wsum[wid] = v;
    __syncthreads();
    if (wid == 0) {
        int w = wsum[lane];
#pragma unroll
        for (int o = 1; o < 32; o <<= 1) { int n = __shfl_up_sync(FULL, w, o); if (lane >= o) w += n; }
        wsum[lane] = w;
    }
    __syncthreads();
    int run = (v - s) + (wid > 0 ? wsum[wid - 1] : 0);
    for (int j = 0; j < C; j++) {
        int idx = base + j;
        if (idx < NN) { g_off[idx] = run; g_pos[idx] = run; run += g_cnt[idx]; }
    }
    if (t == 1023) g_off[NN] = NE;
}
__global__ void place_edges(const int* __restrict__ src, const int* __restrict__ dst) {
    int e = blockIdx.x * blockDim.x + threadIdx.x;
    if (e >= NE) return;
    int slot = atomicAdd(&g_pos[dst[e]], 1);
    g_psrc[slot] = src[e];
}

// ---------------- tf32 GEMM with fused attention epilogue (BN=64, 2 CTAs/SM) ---------
// tf32 conversion once on the global->smem path; per-fragment conversion removed.
// EPI==1: layer 1 (2 heads per 64-col block). EPI==2: layer 2 (1 head, 64 dims).
#define LDA 40
#define LDB 72
#define LDC 68
template<bool ELUA, int EPI>
__global__ void __launch_bounds__(256, 2)
gemm_fused(const float* __restrict__ A, const float* __restrict__ B,
           const float* __restrict__ av, const float* __restrict__ rv,
           int M, int K, int Nn) {
    __shared__ float sbuf[128 * LDC];          // 34.8 KB; As+Bs live in the front
    float* As = sbuf;                          // [128][LDA]
    float* Bs = sbuf + 128 * LDA;              // [32][LDB]
    const int tid = threadIdx.x;
    const int wid = tid >> 5;
    const int wm = (wid & 3) * 32;
    const int wn = (wid >> 2) * 32;
    const int rowBase = blockIdx.y * 128;
    const int colBase = blockIdx.x * 64;

    int aRow[4], aK[4];
#pragma unroll
    for (int l = 0; l < 4; l++) {
        int f = tid + l * 256;
        aRow[l] = f >> 3; aK[l] = (f & 7) * 4;
    }
    int bRow[2], bCol[2];
#pragma unroll
    for (int l = 0; l < 2; l++) {
        int f = tid + l * 256;
        bRow[l] = f >> 4; bCol[l] = (f & 15) * 4;
    }

    wmma::fragment<wmma::accumulator, 16, 16, 8, float> acc[2][2];
#pragma unroll
    for (int i = 0; i < 2; i++)
#pragma unroll
        for (int j = 0; j < 2; j++) wmma::fill_fragment(acc[i][j], 0.f);

    float4 pa[4], pb[2];
#pragma unroll
    for (int l = 0; l < 4; l++) {
        pa[l] = make_float4(0.f, 0.f, 0.f, 0.f);
        if (rowBase + aRow[l] < M) pa[l] = *(const float4*)&A[(size_t)(rowBase + aRow[l]) * K + aK[l]];
    }
#pragma unroll
    for (int l = 0; l < 2; l++)
        pb[l] = *(const float4*)&B[(size_t)bRow[l] * Nn + colBase + bCol[l]];

    for (int k0 = 0; k0 < K; k0 += 32) {
#pragma unroll
        for (int l = 0; l < 4; l++) {
            float4 sa = pa[l];
            if (ELUA) {
                sa.x = sa.x > 0.f ? sa.x : expm1f(sa.x);
                sa.y = sa.y > 0.f ? sa.y : expm1f(sa.y);
                sa.z = sa.z > 0.f ? sa.z : expm1f(sa.z);
                sa.w = sa.w > 0.f ? sa.w : expm1f(sa.w);
            }
            sa = tf32_f4(sa);
            float* p = &As[aRow[l] * LDA + aK[l]];
            p[0] = sa.x; p[1] = sa.y; p[2] = sa.z; p[3] = sa.w;
        }
#pragma unroll
        for (int l = 0; l < 2; l++) {
            float4 sb = tf32_f4(pb[l]);
            float* p = &Bs[bRow[l] * LDB + bCol[l]];
            p[0] = sb.x; p[1] = sb.y; p[2] = sb.z; p[3] = sb.w;
        }
        __syncthreads();

        if (k0 + 32 < K) {
#pragma unroll
            for (int l = 0; l < 4; l++)
                if (rowBase + aRow[l] < M)
                    pa[l] = *(const float4*)&A[(size_t)(rowBase + aRow[l]) * K + (k0 + 32) + aK[l]];
#pragma unroll
            for (int l = 0; l < 2; l++)
                pb[l] = *(const float4*)&B[(size_t)(k0 + 32 + bRow[l]) * Nn + colBase + bCol[l]];
        }

#pragma unroll
        for (int kk = 0; kk < 32; kk += 8) {
            wmma::fragment<wmma::matrix_a, 16, 16, 8, wmma::precision::tf32, wmma::row_major> af[2];
            wmma::fragment<wmma::matrix_b, 16, 16, 8, wmma::precision::tf32, wmma::row_major> bf[2];
#pragma unroll
            for (int i = 0; i < 2; i++)
                wmma::load_matrix_sync(af[i], &As[(wm + i * 16) * LDA + kk], LDA);
#pragma unroll
            for (int j = 0; j < 2; j++)
                wmma::load_matrix_sync(bf[j], &Bs[kk * LDB + wn + j * 16], LDB);
#pragma unroll
            for (int i = 0; i < 2; i++)
#pragma unroll
                for (int j = 0; j < 2; j++)
                    wmma::mma_sync(acc[i][j], af[i], bf[j], acc[i][j]);
        }
        __syncthreads();
    }

    // ---- epilogue: stage tile in smem, emit el/er + fp16 table ----
#pragma unroll
    for (int i = 0; i < 2; i++)
#pragma unroll
        for (int j = 0; j < 2; j++)
            wmma::store_matrix_sync(&sbuf[(wm + i * 16) * LDC + wn + j * 16], acc[i][j],
                                    LDC, wmma::mem_row_major);
    __syncthreads();

    const int row  = tid >> 1;
    const int half = tid & 1;
    const int gr   = rowBase + row;
    const float* crow = &sbuf[row * LDC + half * 32];
    const int head = (EPI == 1) ? ((colBase >> 5) + half) : 0;
    const float* ap = (EPI == 1) ? av + head * HID : av + half * 32;
    const float* rp = (EPI == 1) ? rv + head * HID : rv + half * 32;

    float el = 0.f, er = 0.f;
    unsigned w[16];
#pragma unroll
    for (int d = 0; d < 32; d += 2) {
        float c0 = crow[d], c1 = crow[d + 1];
        el += c0 * ap[d] + c1 * ap[d + 1];
        er += c0 * rp[d] + c1 * rp[d + 1];
        __half2 hh = __floats2half2_rn(c0, c1);
        w[d >> 1] = *(unsigned*)&hh;
    }

    if (EPI == 1) {
        if (gr < NN) {
            g_el1[gr * HEADS + head] = el;
            g_er1[gr * HEADS + head] = er;
            uint4* d4 = (uint4*)&g_f1h[(size_t)gr * F1DIM + colBase + half * 32];
            const uint4* s4 = (const uint4*)w;
            d4[0] = s4[0]; d4[1] = s4[1]; d4[2] = s4[2]; d4[3] = s4[3];
        }
    } else {
        float elf = el + __shfl_xor_sync(FULL, el, 1);
        float erf = er + __shfl_xor_sync(FULL, er, 1);
        if (gr < NN) {
            if (half == 0) { g_el2[gr] = elf; g_er2[gr] = erf; }
            uint4* d4 = (uint4*)&g_f2h[(size_t)gr * ODIM + half * 32];
            const uint4* s4 = (const uint4*)w;
            d4[0] = s4[0]; d4[1] = s4[1]; d4[2] = s4[2]; d4[3] = s4[3];
        }
    }
}

// ---------------- layer-1 aggregation: warp/node, single pass, fp16 gather, 4x unroll --
__global__ void __launch_bounds__(256)
agg1(const float* __restrict__ b1) {
    int warp = (blockIdx.x * blockDim.x + threadIdx.x) >> 5;
    if (warp >= NN) return;
    const int lane = threadIdx.x & 31;
    const int node = warp;
    const int h4 = lane >> 2;
    const int beg = g_off[node], end = g_off[node + 1];

    const float er = g_er1[node * HEADS + h4];

    float acc[8];
#pragma unroll
    for (int j = 0; j < 8; j++) acc[j] = 0.f;
    float ssum = 0.f;

    int i = beg;
    for (; i + 4 <= end; i += 4) {
        int s0 = g_psrc[i], s1 = g_psrc[i + 1], s2 = g_psrc[i + 2], s3 = g_psrc[i + 3];
        float a0 = __expf(lrelu(g_el1[s0 * HEADS + h4] + er));
        float a1 = __expf(lrelu(g_el1[s1 * HEADS + h4] + er));
        float a2 = __expf(lrelu(g_el1[s2 * HEADS + h4] + er));
        float a3 = __expf(lrelu(g_el1[s3 * HEADS + h4] + er));
        uint4 u0 = *(const uint4*)&g_f1h[(size_t)s0 * F1DIM + lane * 8];
        uint4 u1 = *(const uint4*)&g_f1h[(size_t)s1 * F1DIM + lane * 8];
        uint4 u2 = *(const uint4*)&g_f1h[(size_t)s2 * F1DIM + lane * 8];
        uint4 u3 = *(const uint4*)&g_f1h[(size_t)s3 * F1DIM + lane * 8];
        ssum += (a0 + a1) + (a2 + a3);
        const __half2* p0 = (const __half2*)&u0;
        const __half2* p1 = (const __half2*)&u1;
        const __half2* p2 = (const __half2*)&u2;
        const __half2* p3 = (const __half2*)&u3;
#pragma unroll
        for (int j = 0; j < 4; j++) {
            float2 f0 = __half22float2(p0[j]);
            float2 f1 = __half22float2(p1[j]);
            float2 f2 = __half22float2(p2[j]);
            float2 f3 = __half22float2(p3[j]);
            acc[2*j + 0] += (a0 * f0.x + a1 * f1.x) + (a2 * f2.x + a3 * f3.x);
            acc[2*j + 1] += (a0 * f0.y + a1 * f1.y) + (a2 * f2.y + a3 * f3.y);
        }
    }
    for (; i < end; i++) {
        int s0 = g_psrc[i];
        float a0 = __expf(lrelu(g_el1[s0 * HEADS + h4] + er));
        uint4 u0 = *(const uint4*)&g_f1h[(size_t)s0 * F1DIM + lane * 8];
        ssum += a0;
        const __half2* p0 = (const __half2*)&u0;
#pragma unroll
        for (int j = 0; j < 4; j++) {
            float2 f0 = __half22float2(p0[j]);
            acc[2*j + 0] += a0 * f0.x;
            acc[2*j + 1] += a0 * f0.y;
        }
    }

    const float inv = ssum > 0.f ? 1.f / ssum : 0.f;
    const float4* bp = (const float4*)&b1[lane * 8];
    float4 bb0 = bp[0], bb1 = bp[1];
    float4* op = (float4*)&g_h[(size_t)node * F1DIM + lane * 8];
    op[0] = make_float4(acc[0] * inv + bb0.x, acc[1] * inv + bb0.y,
                        acc[2] * inv + bb0.z, acc[3] * inv + bb0.w);
    op[1] = make_float4(acc[4] * inv + bb1.x, acc[5] * inv + bb1.y,
                        acc[6] * inv + bb1.z, acc[7] * inv + bb1.w);
}

// ---------------- layer-2 aggregation: warp/node, single pass, fp16 gather ----------
__global__ void __launch_bounds__(256)
agg2(float* __restrict__ out, const float* __restrict__ b2) {
    int warp = (blockIdx.x * blockDim.x + threadIdx.x) >> 5;
    if (warp >= NN) return;
    const int lane = threadIdx.x & 31;
    const int node = warp;
    const int beg = g_off[node], end = g_off[node + 1];

    const float er = g_er2[node];

    float a0 = 0.f, a1 = 0.f, ssum = 0.f;
    int i = beg;
    for (; i + 4 <= end; i += 4) {
        int s0 = g_psrc[i], s1 = g_psrc[i+1], s2 = g_psrc[i+2], s3 = g_psrc[i+3];
        float e0 = __expf(lrelu(g_el2[s0] + er));
        float e1 = __expf(lrelu(g_el2[s1] + er));
        float e2 = __expf(lrelu(g_el2[s2] + er));
        float e3 = __expf(lrelu(g_el2[s3] + er));
        float2 v0 = __half22float2(*(const __half2*)&g_f2h[(size_t)s0 * ODIM + lane * 2]);
        float2 v1 = __half22float2(*(const __half2*)&g_f2h[(size_t)s1 * ODIM + lane * 2]);
        float2 v2 = __half22float2(*(const __half2*)&g_f2h[(size_t)s2 * ODIM + lane * 2]);
        float2 v3 = __half22float2(*(const __half2*)&g_f2h[(size_t)s3 * ODIM + lane * 2]);
        ssum += (e0 + e1) + (e2 + e3);
        a0 += e0 * v0.x + e1 * v1.x + e2 * v2.x + e3 * v3.x;
        a1 += e0 * v0.y + e1 * v1.y + e2 * v2.y + e3 * v3.y;
    }
    for (; i < end; i++) {
        int s = g_psrc[i];
        float e0 = __expf(lrelu(g_el2[s] + er));
        float2 v = __half22float2(*(const __half2*)&g_f2h[(size_t)s * ODIM + lane * 2]);
        ssum += e0;
        a0 += e0 * v.x;
        a1 += e0 * v.y;
    }
    const float inv = ssum > 0.f ? 1.f / ssum : 0.f;
    float2 bb = *(const float2*)&b2[lane * 2];
    *(float2*)&out[(size_t)node * ODIM + lane * 2] = make_float2(a0 * inv + bb.x, a1 * inv + bb.y);
}

// ---------------- launch ----------------
extern "C" void kernel_launch(void* const* d_in, const int* in_sizes, int n_in,
                              void* d_out, int out_size) {
    const float* feat = (const float*)d_in[0];
    const int*   src  = (const int*)  d_in[1];
    const int*   dst  = (const int*)  d_in[2];
    const float* W1   = (const float*)d_in[3];
    const float* al1  = (const float*)d_in[4];
    const float* ar1  = (const float*)d_in[5];
    const float* b1   = (const float*)d_in[6];
    const float* W2   = (const float*)d_in[7];
    const float* al2  = (const float*)d_in[8];
    const float* ar2  = (const float*)d_in[9];
    const float* b2   = (const float*)d_in[10];
    float* out = (float*)d_out;

    float* ph;
    cudaGetSymbolAddress((void**)&ph, g_h);

    const int T = 256;
    auto cdiv = [](long long a, long long b) { return (int)((a + b - 1) / b); };

    // CSR build (shared by both layers)
    zero_cnt<<<cdiv(NN, T), T>>>();
    count_dst<<<cdiv(NE, T), T>>>(dst);
    scan_off<<<1, 1024>>>();
    place_edges<<<cdiv(NE, T), T>>>(src, dst);

    // Layer 1: f1h/el1/er1 = fused(feat @ W1), BN=64
    gemm_fused<false, 1><<<dim3(F1DIM / 64, NNP / 128), 256>>>(feat, W1, al1, ar1, NN, IN_DIM, F1DIM);
    agg1<<<cdiv((long long)NN * 32, T), T>>>(b1);

    // Layer 2: f2h/el2/er2 = fused(ELU(g_h) @ W2), BN=64; g_h pad rows stay 0 -> safe
    gemm_fused<true, 2><<<dim3(ODIM / 64, NNP / 128), 256>>>(ph, W2, al2, ar2, NNP, F1DIM, ODIM);
    agg2<<<cdiv((long long)NN * 32, T), T>>>(out, b2);
}

// round 15
// speedup vs baseline: 1.1556x; 1.0998x over previous
#include <cuda_runtime.h>
#include <cuda_fp16.h>
#include <mma.h>
#include <math.h>

using namespace nvcuda;

#define NN 50000
#define NNP 50048            // padded rows (= 391 * 128) for unguarded tiles
#define NE 800000
#define IN_DIM 128
#define HID 32
#define HEADS 8
#define F1DIM 256
#define ODIM 64
#define NEG 0.2f
#define FULL 0xffffffffu

// ---------------- scratch (device globals; no allocation) ----------------
__device__ alignas(16) __half g_f1h[(size_t)NN  * F1DIM];  // fp16 gather table, layer 1
__device__ alignas(16) __half g_hh [(size_t)NNP * F1DIM];  // ELU(h) in fp16; pad rows stay 0
__device__ alignas(16) __half g_f2h[(size_t)NN  * ODIM];   // fp16 gather table, layer 2
__device__ float g_el1[NN * HEADS];
__device__ float g_er1[NN * HEADS];
__device__ float g_el2[NN];
__device__ float g_er2[NN];
__device__ int g_cnt [NN];
__device__ int g_off [NN + 1];
__device__ int g_pos [NN];
__device__ int g_psrc[NE];

__device__ __forceinline__ float lrelu(float x) { return x >= 0.f ? x : NEG * x; }
__device__ __forceinline__ float4 tf32_f4(float4 v) {
    v.x = wmma::__float_to_tf32(v.x); v.y = wmma::__float_to_tf32(v.y);
    v.z = wmma::__float_to_tf32(v.z); v.w = wmma::__float_to_tf32(v.w);
    return v;
}

// ---------------- CSR build ----------------
__global__ void zero_cnt() {
    int i = blockIdx.x * blockDim.x + threadIdx.x;
    if (i < NN) g_cnt[i] = 0;
}
__global__ void count_dst(const int* __restrict__ dst) {
    int e = blockIdx.x * blockDim.x + threadIdx.x;
    if (e < NE) atomicAdd(&g_cnt[dst[e]], 1);
}
__global__ void scan_off() {
    __shared__ int wsum[32];
    const int t = threadIdx.x;
    const int C = (NN + 1023) / 1024;
    const int base = t * C;
    int s = 0;
    for (int j = 0; j < C; j++) { int idx = base + j; if (idx < NN) s += g_cnt[idx]; }
    int lane = t & 31, wid = t >> 5;
    int v = s;
#pragma unroll
    for (int o = 1; o < 32; o <<= 1) { int n = __shfl_up_sync(FULL, v, o); if (lane >= o) v += n; }
    if (lane == 31) wsum[wid] = v;
    __syncthreads();
    if (wid == 0) {
        int w = wsum[lane];
#pragma unroll
        for (int o = 1; o < 32; o <<= 1) { int n = __shfl_up_sync(FULL, w, o); if (lane >= o) w += n; }
        wsum[lane] = w;
    }
    __syncthreads();
    int run = (v - s) + (wid > 0 ? wsum[wid - 1] : 0);
    for (int j = 0; j < C; j++) {
        int idx = base + j;
        if (idx < NN) { g_off[idx] = run; g_pos[idx] = run; run += g_cnt[idx]; }
    }
    if (t == 1023) g_off[NN] = NE;
}
__global__ void place_edges(const int* __restrict__ src, const int* __restrict__ dst) {
    int e = blockIdx.x * blockDim.x + threadIdx.x;
    if (e >= NE) return;
    int slot = atomicAdd(&g_pos[dst[e]], 1);
    g_psrc[slot] = src[e];
}

// ---------------- layer-1: tf32 GEMM with fused attention epilogue (BN=64) -----------
#define LDA 40
#define LDB 72
#define LDC 68
__global__ void __launch_bounds__(256, 2)
gemm1_fused(const float* __restrict__ A, const float* __restrict__ B,
            const float* __restrict__ av, const float* __restrict__ rv,
            int M, int K, int Nn) {
    __shared__ float sbuf[128 * LDC];
    float* As = sbuf;
    float* Bs = sbuf + 128 * LDA;
    const int tid = threadIdx.x;
    const int wid = tid >> 5;
    const int wm = (wid & 3) * 32;
    const int wn = (wid >> 2) * 32;
    const int rowBase = blockIdx.y * 128;
    const int colBase = blockIdx.x * 64;

    int aRow[4], aK[4];
#pragma unroll
    for (int l = 0; l < 4; l++) {
        int f = tid + l * 256;
        aRow[l] = f >> 3; aK[l] = (f & 7) * 4;
    }
    int bRow[2], bCol[2];
#pragma unroll
    for (int l = 0; l < 2; l++) {
        int f = tid + l * 256;
        bRow[l] = f >> 4; bCol[l] = (f & 15) * 4;
    }

    wmma::fragment<wmma::accumulator, 16, 16, 8, float> acc[2][2];
#pragma unroll
    for (int i = 0; i < 2; i++)
#pragma unroll
        for (int j = 0; j < 2; j++) wmma::fill_fragment(acc[i][j], 0.f);

    float4 pa[4], pb[2];
#pragma unroll
    for (int l = 0; l < 4; l++) {
        pa[l] = make_float4(0.f, 0.f, 0.f, 0.f);
        if (rowBase + aRow[l] < M) pa[l] = *(const float4*)&A[(size_t)(rowBase + aRow[l]) * K + aK[l]];
    }
#pragma unroll
    for (int l = 0; l < 2; l++)
        pb[l] = *(const float4*)&B[(size_t)bRow[l] * Nn + colBase + bCol[l]];

    for (int k0 = 0; k0 < K; k0 += 32) {
#pragma unroll
        for (int l = 0; l < 4; l++) {
            float4 sa = tf32_f4(pa[l]);
            float* p = &As[aRow[l] * LDA + aK[l]];
            p[0] = sa.x; p[1] = sa.y; p[2] = sa.z; p[3] = sa.w;
        }
#pragma unroll
        for (int l = 0; l < 2; l++) {
            float4 sb = tf32_f4(pb[l]);
            float* p = &Bs[bRow[l] * LDB + bCol[l]];
            p[0] = sb.x; p[1] = sb.y; p[2] = sb.z; p[3] = sb.w;
        }
        __syncthreads();

        if (k0 + 32 < K) {
#pragma unroll
            for (int l = 0; l < 4; l++)
                if (rowBase + aRow[l] < M)
                    pa[l] = *(const float4*)&A[(size_t)(rowBase + aRow[l]) * K + (k0 + 32) + aK[l]];
#pragma unroll
            for (int l = 0; l < 2; l++)
                pb[l] = *(const float4*)&B[(size_t)(k0 + 32 + bRow[l]) * Nn + colBase + bCol[l]];
        }

#pragma unroll
        for (int kk = 0; kk < 32; kk += 8) {
            wmma::fragment<wmma::matrix_a, 16, 16, 8, wmma::precision::tf32, wmma::row_major> af[2];
            wmma::fragment<wmma::matrix_b, 16, 16, 8, wmma::precision::tf32, wmma::row_major> bf[2];
#pragma unroll
            for (int i = 0; i < 2; i++)
                wmma::load_matrix_sync(af[i], &As[(wm + i * 16) * LDA + kk], LDA);
#pragma unroll
            for (int j = 0; j < 2; j++)
                wmma::load_matrix_sync(bf[j], &Bs[kk * LDB + wn + j * 16], LDB);
#pragma unroll
            for (int i = 0; i < 2; i++)
#pragma unroll
                for (int j = 0; j < 2; j++)
                    wmma::mma_sync(acc[i][j], af[i], bf[j], acc[i][j]);
        }
        __syncthreads();
    }

#pragma unroll
    for (int i = 0; i < 2; i++)
#pragma unroll
        for (int j = 0; j < 2; j++)
            wmma::store_matrix_sync(&sbuf[(wm + i * 16) * LDC + wn + j * 16], acc[i][j],
                                    LDC, wmma::mem_row_major);
    __syncthreads();

    const int row  = tid >> 1;
    const int half = tid & 1;
    const int gr   = rowBase + row;
    const float* crow = &sbuf[row * LDC + half * 32];
    const int head = (colBase >> 5) + half;
    const float* ap = av + head * HID;
    const float* rp = rv + head * HID;

    float el = 0.f, er = 0.f;
    unsigned w[16];
#pragma unroll
    for (int d = 0; d < 32; d += 2) {
        float c0 = crow[d], c1 = crow[d + 1];
        el += c0 * ap[d] + c1 * ap[d + 1];
        er += c0 * rp[d] + c1 * rp[d + 1];
        __half2 hh = __floats2half2_rn(c0, c1);
        w[d >> 1] = *(unsigned*)&hh;
    }
    if (gr < NN) {
        g_el1[gr * HEADS + head] = el;
        g_er1[gr * HEADS + head] = er;
        uint4* d4 = (uint4*)&g_f1h[(size_t)gr * F1DIM + colBase + half * 32];
        const uint4* s4 = (const uint4*)w;
        d4[0] = s4[0]; d4[1] = s4[1]; d4[2] = s4[2]; d4[3] = s4[3];
    }
}

// ---------------- layer-2: fp16 GEMM (A = g_hh) with fused attention epilogue --------
// 16x16x16 half MMA, fp32 accum. A already ELU'd fp16; B = W2 converted on load.
#define LDA2 40   // halves
#define LDB2 72   // halves
__global__ void __launch_bounds__(256, 2)
gemm2_fused(const __half* __restrict__ A, const float* __restrict__ B,
            const float* __restrict__ av, const float* __restrict__ rv,
            int K, int Nn) {
    __shared__ float sbuf[128 * LDC];          // epilogue stage; front reused for As/Bs
    __half* As = (__half*)sbuf;                // [128][LDA2] halves
    __half* Bs = As + 128 * LDA2;              // [32][LDB2] halves
    const int tid = threadIdx.x;
    const int wid = tid >> 5;
    const int wm = (wid & 3) * 32;
    const int wn = (wid >> 2) * 32;
    const int rowBase = blockIdx.y * 128;

    // A: 128x32 halves -> 2 uint4 (8 halves) per thread
    int aRow[2], aK[2];
#pragma unroll
    for (int l = 0; l < 2; l++) {
        int f = tid + l * 256;
        aRow[l] = f >> 2; aK[l] = (f & 3) * 8;
    }
    // B: 32x64 -> 8 halves per thread (from 2 float4 of W2)
    const int bRow = tid >> 3;
    const int bCol = (tid & 7) * 8;

    wmma::fragment<wmma::accumulator, 16, 16, 16, float> acc[2][2];
#pragma unroll
    for (int i = 0; i < 2; i++)
#pragma unroll
        for (int j = 0; j < 2; j++) wmma::fill_fragment(acc[i][j], 0.f);

    uint4 pa[2];
    float4 pb0, pb1;
#pragma unroll
    for (int l = 0; l < 2; l++)
        pa[l] = *(const uint4*)&A[(size_t)(rowBase + aRow[l]) * K + aK[l]];
    pb0 = *(const float4*)&B[(size_t)bRow * Nn + bCol];
    pb1 = *(const float4*)&B[(size_t)bRow * Nn + bCol + 4];

    for (int k0 = 0; k0 < K; k0 += 32) {
#pragma unroll
        for (int l = 0; l < 2; l++)
            *(uint4*)&As[aRow[l] * LDA2 + aK[l]] = pa[l];
        {
            __half2 h0 = __floats2half2_rn(pb0.x, pb0.y);
            __half2 h1 = __floats2half2_rn(pb0.z, pb0.w);
            __half2 h2 = __floats2half2_rn(pb1.x, pb1.y);
            __half2 h3 = __floats2half2_rn(pb1.z, pb1.w);
            *(uint4*)&Bs[bRow * LDB2 + bCol] =
                make_uint4(*(unsigned*)&h0, *(unsigned*)&h1, *(unsigned*)&h2, *(unsigned*)&h3);
        }
        __syncthreads();

        if (k0 + 32 < K) {
#pragma unroll
            for (int l = 0; l < 2; l++)
                pa[l] = *(const uint4*)&A[(size_t)(rowBase + aRow[l]) * K + (k0 + 32) + aK[l]];
            pb0 = *(const float4*)&B[(size_t)(k0 + 32 + bRow) * Nn + bCol];
            pb1 = *(const float4*)&B[(size_t)(k0 + 32 + bRow) * Nn + bCol + 4];
        }

#pragma unroll
        for (int kk = 0; kk < 32; kk += 16) {
            wmma::fragment<wmma::matrix_a, 16, 16, 16, __half, wmma::row_major> af[2];
            wmma::fragment<wmma::matrix_b, 16, 16, 16, __half, wmma::row_major> bf[2];
#pragma unroll
            for (int i = 0; i < 2; i++)
                wmma::load_matrix_sync(af[i], &As[(wm + i * 16) * LDA2 + kk], LDA2);
#pragma unroll
            for (int j = 0; j < 2; j++)
                wmma::load_matrix_sync(bf[j], &Bs[kk * LDB2 + wn + j * 16], LDB2);
#pragma unroll
            for (int i = 0; i < 2; i++)
#pragma unroll
                for (int j = 0; j < 2; j++)
                    wmma::mma_sync(acc[i][j], af[i], bf[j], acc[i][j]);
        }
        __syncthreads();
    }

#pragma unroll
    for (int i = 0; i < 2; i++)
#pragma unroll
        for (int j = 0; j < 2; j++)
            wmma::store_matrix_sync(&sbuf[(wm + i * 16) * LDC + wn + j * 16], acc[i][j],
                                    LDC, wmma::mem_row_major);
    __syncthreads();

    const int row  = tid >> 1;
    const int half = tid & 1;
    const int gr   = rowBase + row;
    const float* crow = &sbuf[row * LDC + half * 32];
    const float* ap = av + half * 32;
    const float* rp = rv + half * 32;

    float el = 0.f, er = 0.f;
    unsigned w[16];
#pragma unroll
    for (int d = 0; d < 32; d += 2) {
        float c0 = crow[d], c1 = crow[d + 1];
        el += c0 * ap[d] + c1 * ap[d + 1];
        er += c0 * rp[d] + c1 * rp[d + 1];
        __half2 hh = __floats2half2_rn(c0, c1);
        w[d >> 1] = *(unsigned*)&hh;
    }
    float elf = el + __shfl_xor_sync(FULL, el, 1);
    float erf = er + __shfl_xor_sync(FULL, er, 1);
    if (gr < NN) {
        if (half == 0) { g_el2[gr] = elf; g_er2[gr] = erf; }
        uint4* d4 = (uint4*)&g_f2h[(size_t)gr * ODIM + half * 32];
        const uint4* s4 = (const uint4*)w;
        d4[0] = s4[0]; d4[1] = s4[1]; d4[2] = s4[2]; d4[3] = s4[3];
    }
}

// ---------------- layer-1 aggregation: warp/node, single pass, fp16 gather, 4x unroll --
// Epilogue: h = ELU(acc*inv + b1) stored fp16 to g_hh.
__global__ void __launch_bounds__(256)
agg1(const float* __restrict__ b1) {
    int warp = (blockIdx.x * blockDim.x + threadIdx.x) >> 5;
    if (warp >= NN) return;
    const int lane = threadIdx.x & 31;
    const int node = warp;
    const int h4 = lane >> 2;
    const int beg = g_off[node], end = g_off[node + 1];

    const float er = g_er1[node * HEADS + h4];

    float acc[8];
#pragma unroll
    for (int j = 0; j < 8; j++) acc[j] = 0.f;
    float ssum = 0.f;

    int i = beg;
    for (; i + 4 <= end; i += 4) {
        int s0 = g_psrc[i], s1 = g_psrc[i + 1], s2 = g_psrc[i + 2], s3 = g_psrc[i + 3];
        float a0 = __expf(lrelu(g_el1[s0 * HEADS + h4] + er));
        float a1 = __expf(lrelu(g_el1[s1 * HEADS + h4] + er));
        float a2 = __expf(lrelu(g_el1[s2 * HEADS + h4] + er));
        float a3 = __expf(lrelu(g_el1[s3 * HEADS + h4] + er));
        uint4 u0 = *(const uint4*)&g_f1h[(size_t)s0 * F1DIM + lane * 8];
        uint4 u1 = *(const uint4*)&g_f1h[(size_t)s1 * F1DIM + lane * 8];
        uint4 u2 = *(const uint4*)&g_f1h[(size_t)s2 * F1DIM + lane * 8];
        uint4 u3 = *(const uint4*)&g_f1h[(size_t)s3 * F1DIM + lane * 8];
        ssum += (a0 + a1) + (a2 + a3);
        const __half2* p0 = (const __half2*)&u0;
        const __half2* p1 = (const __half2*)&u1;
        const __half2* p2 = (const __half2*)&u2;
        const __half2* p3 = (const __half2*)&u3;
#pragma unroll
        for (int j = 0; j < 4; j++) {
            float2 f0 = __half22float2(p0[j]);
            float2 f1 = __half22float2(p1[j]);
            float2 f2 = __half22float2(p2[j]);
            float2 f3 = __half22float2(p3[j]);
            acc[2*j + 0] += (a0 * f0.x + a1 * f1.x) + (a2 * f2.x + a3 * f3.x);
            acc[2*j + 1] += (a0 * f0.y + a1 * f1.y) + (a2 * f2.y + a3 * f3.y);
        }
    }
    for (; i < end; i++) {
        int s0 = g_psrc[i];
        float a0 = __expf(lrelu(g_el1[s0 * HEADS + h4] + er));
        uint4 u0 = *(const uint4*)&g_f1h[(size_t)s0 * F1DIM + lane * 8];
        ssum += a0;
        const __half2* p0 = (const __half2*)&u0;
#pragma unroll
        for (int j = 0; j < 4; j++) {
            float2 f0 = __half22float2(p0[j]);
            acc[2*j + 0] += a0 * f0.x;
            acc[2*j + 1] += a0 * f0.y;
        }
    }

    const float inv = ssum > 0.f ? 1.f / ssum : 0.f;
    const float4* bp = (const float4*)&b1[lane * 8];
    float4 bb0 = bp[0], bb1 = bp[1];
    float hv[8];
    hv[0] = acc[0] * inv + bb0.x; hv[1] = acc[1] * inv + bb0.y;
    hv[2] = acc[2] * inv + bb0.z; hv[3] = acc[3] * inv + bb0.w;
    hv[4] = acc[4] * inv + bb1.x; hv[5] = acc[5] * inv + bb1.y;
    hv[6] = acc[6] * inv + bb1.z; hv[7] = acc[7] * inv + bb1.w;
    unsigned w[4];
#pragma unroll
    for (int j = 0; j < 4; j++) {
        float x0 = hv[2*j],   e0 = x0 > 0.f ? x0 : expm1f(x0);
        float x1 = hv[2*j+1], e1 = x1 > 0.f ? x1 : expm1f(x1);
        __half2 hh = __floats2half2_rn(e0, e1);
        w[j] = *(unsigned*)&hh;
    }
    *(uint4*)&g_hh[(size_t)node * F1DIM + lane * 8] = *(const uint4*)w;
}

// ---------------- layer-2 aggregation: warp/node, single pass, fp16 gather ----------
__global__ void __launch_bounds__(256)
agg2(float* __restrict__ out, const float* __restrict__ b2) {
    int warp = (blockIdx.x * blockDim.x + threadIdx.x) >> 5;
    if (warp >= NN) return;
    const int lane = threadIdx.x & 31;
    const int node = warp;
    const int beg = g_off[node], end = g_off[node + 1];

    const float er = g_er2[node];

    float a0 = 0.f, a1 = 0.f, ssum = 0.f;
    int i = beg;
    for (; i + 4 <= end; i += 4) {
        int s0 = g_psrc[i], s1 = g_psrc[i+1], s2 = g_psrc[i+2], s3 = g_psrc[i+3];
        float e0 = __expf(lrelu(g_el2[s0] + er));
        float e1 = __expf(lrelu(g_el2[s1] + er));
        float e2 = __expf(lrelu(g_el2[s2] + er));
        float e3 = __expf(lrelu(g_el2[s3] + er));
        float2 v0 = __half22float2(*(const __half2*)&g_f2h[(size_t)s0 * ODIM + lane * 2]);
        float2 v1 = __half22float2(*(const __half2*)&g_f2h[(size_t)s1 * ODIM + lane * 2]);
        float2 v2 = __half22float2(*(const __half2*)&g_f2h[(size_t)s2 * ODIM + lane * 2]);
        float2 v3 = __half22float2(*(const __half2*)&g_f2h[(size_t)s3 * ODIM + lane * 2]);
        ssum += (e0 + e1) + (e2 + e3);
        a0 += e0 * v0.x + e1 * v1.x + e2 * v2.x + e3 * v3.x;
        a1 += e0 * v0.y + e1 * v1.y + e2 * v2.y + e3 * v3.y;
    }
    for (; i < end; i++) {
        int s = g_psrc[i];
        float e0 = __expf(lrelu(g_el2[s] + er));
        float2 v = __half22float2(*(const __half2*)&g_f2h[(size_t)s * ODIM + lane * 2]);
        ssum += e0;
        a0 += e0 * v.x;
        a1 += e0 * v.y;
    }
    const float inv = ssum > 0.f ? 1.f / ssum : 0.f;
    float2 bb = *(const float2*)&b2[lane * 2];
    *(float2*)&out[(size_t)node * ODIM + lane * 2] = make_float2(a0 * inv + bb.x, a1 * inv + bb.y);
}

// ---------------- launch ----------------
extern "C" void kernel_launch(void* const* d_in, const int* in_sizes, int n_in,
                              void* d_out, int out_size) {
    const float* feat = (const float*)d_in[0];
    const int*   src  = (const int*)  d_in[1];
    const int*   dst  = (const int*)  d_in[2];
    const float* W1   = (const float*)d_in[3];
    const float* al1  = (const float*)d_in[4];
    const float* ar1  = (const float*)d_in[5];
    const float* b1   = (const float*)d_in[6];
    const float* W2   = (const float*)d_in[7];
    const float* al2  = (const float*)d_in[8];
    const float* ar2  = (const float*)d_in[9];
    const float* b2   = (const float*)d_in[10];
    float* out = (float*)d_out;

    __half* phh;
    cudaGetSymbolAddress((void**)&phh, g_hh);

    const int T = 256;
    auto cdiv = [](long long a, long long b) { return (int)((a + b - 1) / b); };

    // CSR build (shared by both layers)
    zero_cnt<<<cdiv(NN, T), T>>>();
    count_dst<<<cdiv(NE, T), T>>>(dst);
    scan_off<<<1, 1024>>>();
    place_edges<<<cdiv(NE, T), T>>>(src, dst);

    // Layer 1: f1h/el1/er1 = fused(feat @ W1), tf32
    gemm1_fused<<<dim3(F1DIM / 64, NNP / 128), 256>>>(feat, W1, al1, ar1, NN, IN_DIM, F1DIM);
    agg1<<<cdiv((long long)NN * 32, T), T>>>(b1);

    // Layer 2: f2h/el2/er2 = fused(g_hh @ W2), fp16 MMA; g_hh pad rows stay 0 -> safe
    gemm2_fused<<<dim3(1, NNP / 128), 256>>>(phh, W2, al2, ar2, F1DIM, ODIM);
    agg2<<<cdiv((long long)NN * 32, T), T>>>(out, b2);
}

// round 16
// speedup vs baseline: 1.3200x; 1.1422x over previous
#include <cuda_runtime.h>
#include <cuda_fp16.h>
#include <mma.h>
#include <math.h>

using namespace nvcuda;

#define NN 50000
#define NNP 50048            // padded rows (= 391 * 128) for unguarded tiles
#define NE 800000
#define IN_DIM 128
#define HID 32
#define HEADS 8
#define F1DIM 256
#define ODIM 64
#define NEG 0.2f
#define FULL 0xffffffffu

// ---------------- scratch (device globals; no allocation) ----------------
__device__ alignas(16) __half g_f1h[(size_t)NN  * F1DIM];  // fp16 gather table, layer 1
__device__ alignas(16) __half g_hh [(size_t)NNP * F1DIM];  // ELU(h) in fp16; pad rows stay 0
__device__ alignas(16) __half g_f2h[(size_t)NN  * ODIM];   // fp16 gather table, layer 2
__device__ float g_el1[NN * HEADS];
__device__ float g_er1[NN * HEADS];
__device__ float g_el2[NN];
__device__ float g_er2[NN];
__device__ int g_cnt [NN];
__device__ int g_off [NN + 1];
__device__ int g_pos [NN];
__device__ int g_psrc[NE];

__device__ __forceinline__ float lrelu(float x) { return x >= 0.f ? x : NEG * x; }

// ---------------- CSR build ----------------
__global__ void zero_cnt() {
    int i = blockIdx.x * blockDim.x + threadIdx.x;
    if (i < NN) g_cnt[i] = 0;
}
__global__ void count_dst(const int* __restrict__ dst) {
    int e = blockIdx.x * blockDim.x + threadIdx.x;
    if (e < NE) atomicAdd(&g_cnt[dst[e]], 1);
}
__global__ void scan_off() {
    __shared__ int wsum[32];
    const int t = threadIdx.x;
    const int C = (NN + 1023) / 1024;
    const int base = t * C;
    int s = 0;
    for (int j = 0; j < C; j++) { int idx = base + j; if (idx < NN) s += g_cnt[idx]; }
    int lane = t & 31, wid = t >> 5;
    int v = s;
#pragma unroll
    for (int o = 1; o < 32; o <<= 1) { int n = __shfl_up_sync(FULL, v, o); if (lane >= o) v += n; }
    if (lane == 31) wsum[wid] = v;
    __syncthreads();
    if (wid == 0) {
        int w = wsum[lane];
#pragma unroll
        for (int o = 1; o < 32; o <<= 1) { int n = __shfl_up_sync(FULL, w, o); if (lane >= o) w += n; }
        wsum[lane] = w;
    }
    __syncthreads();
    int run = (v - s) + (wid > 0 ? wsum[wid - 1] : 0);
    for (int j = 0; j < C; j++) {
        int idx = base + j;
        if (idx < NN) { g_off[idx] = run; g_pos[idx] = run; run += g_cnt[idx]; }
    }
    if (t == 1023) g_off[NN] = NE;
}
__global__ void place_edges(const int* __restrict__ src, const int* __restrict__ dst) {
    int e = blockIdx.x * blockDim.x + threadIdx.x;
    if (e >= NE) return;
    int slot = atomicAdd(&g_pos[dst[e]], 1);
    g_psrc[slot] = src[e];
}

#define LDC 68
#define LDA2 40   // halves
#define LDB2 72   // halves

// ---------------- layer-1: fp16 GEMM (A,B converted on load) + fused epilogue --------
__global__ void __launch_bounds__(256, 2)
gemm1_fused(const float* __restrict__ A, const float* __restrict__ B,
            const float* __restrict__ av, const float* __restrict__ rv,
            int M, int K, int Nn) {
    __shared__ float sbuf[128 * LDC];
    __half* As = (__half*)sbuf;                // [128][LDA2]
    __half* Bs = As + 128 * LDA2;              // [32][LDB2]
    const int tid = threadIdx.x;
    const int wid = tid >> 5;
    const int wm = (wid & 3) * 32;
    const int wn = (wid >> 2) * 32;
    const int rowBase = blockIdx.y * 128;
    const int colBase = blockIdx.x * 64;

    // A: 128x32 floats -> 1024 float4 -> 4 per thread
    int aRow[4], aK[4];
#pragma unroll
    for (int l = 0; l < 4; l++) {
        int f = tid + l * 256;
        aRow[l] = f >> 3; aK[l] = (f & 7) * 4;
    }
    // B: 32x64 floats -> 8 floats per thread
    const int bRow = tid >> 3;
    const int bCol = (tid & 7) * 8;

    wmma::fragment<wmma::accumulator, 16, 16, 16, float> acc[2][2];
#pragma unroll
    for (int i = 0; i < 2; i++)
#pragma unroll
        for (int j = 0; j < 2; j++) wmma::fill_fragment(acc[i][j], 0.f);

    float4 pa[4], pb0, pb1;
#pragma unroll
    for (int l = 0; l < 4; l++) {
        pa[l] = make_float4(0.f, 0.f, 0.f, 0.f);
        if (rowBase + aRow[l] < M) pa[l] = *(const float4*)&A[(size_t)(rowBase + aRow[l]) * K + aK[l]];
    }
    pb0 = *(const float4*)&B[(size_t)bRow * Nn + colBase + bCol];
    pb1 = *(const float4*)&B[(size_t)bRow * Nn + colBase + bCol + 4];

    for (int k0 = 0; k0 < K; k0 += 32) {
#pragma unroll
        for (int l = 0; l < 4; l++) {
            __half2 h0 = __floats2half2_rn(pa[l].x, pa[l].y);
            __half2 h1 = __floats2half2_rn(pa[l].z, pa[l].w);
            *(uint2*)&As[aRow[l] * LDA2 + aK[l]] = make_uint2(*(unsigned*)&h0, *(unsigned*)&h1);
        }
        {
            __half2 h0 = __floats2half2_rn(pb0.x, pb0.y);
            __half2 h1 = __floats2half2_rn(pb0.z, pb0.w);
            __half2 h2 = __floats2half2_rn(pb1.x, pb1.y);
            __half2 h3 = __floats2half2_rn(pb1.z, pb1.w);
            *(uint4*)&Bs[bRow * LDB2 + bCol] =
                make_uint4(*(unsigned*)&h0, *(unsigned*)&h1, *(unsigned*)&h2, *(unsigned*)&h3);
        }
        __syncthreads();

        if (k0 + 32 < K) {
#pragma unroll
            for (int l = 0; l < 4; l++)
                if (rowBase + aRow[l] < M)
                    pa[l] = *(const float4*)&A[(size_t)(rowBase + aRow[l]) * K + (k0 + 32) + aK[l]];
            pb0 = *(const float4*)&B[(size_t)(k0 + 32 + bRow) * Nn + colBase + bCol];
            pb1 = *(const float4*)&B[(size_t)(k0 + 32 + bRow) * Nn + colBase + bCol + 4];
        }

#pragma unroll
        for (int kk = 0; kk < 32; kk += 16) {
            wmma::fragment<wmma::matrix_a, 16, 16, 16, __half, wmma::row_major> af[2];
            wmma::fragment<wmma::matrix_b, 16, 16, 16, __half, wmma::row_major> bf[2];
#pragma unroll
            for (int i = 0; i < 2; i++)
                wmma::load_matrix_sync(af[i], &As[(wm + i * 16) * LDA2 + kk], LDA2);
#pragma unroll
            for (int j = 0; j < 2; j++)
                wmma::load_matrix_sync(bf[j], &Bs[kk * LDB2 + wn + j * 16], LDB2);
#pragma unroll
            for (int i = 0; i < 2; i++)
#pragma unroll
                for (int j = 0; j < 2; j++)
                    wmma::mma_sync(acc[i][j], af[i], bf[j], acc[i][j]);
        }
        __syncthreads();
    }

#pragma unroll
    for (int i = 0; i < 2; i++)
#pragma unroll
        for (int j = 0; j < 2; j++)
            wmma::store_matrix_sync(&sbuf[(wm + i * 16) * LDC + wn + j * 16], acc[i][j],
                                    LDC, wmma::mem_row_major);
    __syncthreads();

    const int row  = tid >> 1;
    const int half = tid & 1;
    const int gr   = rowBase + row;
    const float* crow = &sbuf[row * LDC + half * 32];
    const int head = (colBase >> 5) + half;
    const float* ap = av + head * HID;
    const float* rp = rv + head * HID;

    float el = 0.f, er = 0.f;
    unsigned w[16];
#pragma unroll
    for (int d = 0; d < 32; d += 2) {
        float c0 = crow[d], c1 = crow[d + 1];
        el += c0 * ap[d] + c1 * ap[d + 1];
        er += c0 * rp[d] + c1 * rp[d + 1];
        __half2 hh = __floats2half2_rn(c0, c1);
        w[d >> 1] = *(unsigned*)&hh;
    }
    if (gr < NN) {
        g_el1[gr * HEADS + head] = el;
        g_er1[gr * HEADS + head] = er;
        uint4* d4 = (uint4*)&g_f1h[(size_t)gr * F1DIM + colBase + half * 32];
        const uint4* s4 = (const uint4*)w;
        d4[0] = s4[0]; d4[1] = s4[1]; d4[2] = s4[2]; d4[3] = s4[3];
    }
}

// ---------------- layer-2: fp16 GEMM (A = g_hh) with fused attention epilogue --------
__global__ void __launch_bounds__(256, 2)
gemm2_fused(const __half* __restrict__ A, const float* __restrict__ B,
            const float* __restrict__ av, const float* __restrict__ rv,
            int K, int Nn) {
    __shared__ float sbuf[128 * LDC];
    __half* As = (__half*)sbuf;
    __half* Bs = As + 128 * LDA2;
    const int tid = threadIdx.x;
    const int wid = tid >> 5;
    const int wm = (wid & 3) * 32;
    const int wn = (wid >> 2) * 32;
    const int rowBase = blockIdx.y * 128;

    int aRow[2], aK[2];
#pragma unroll
    for (int l = 0; l < 2; l++) {
        int f = tid + l * 256;
        aRow[l] = f >> 2; aK[l] = (f & 3) * 8;
    }
    const int bRow = tid >> 3;
    const int bCol = (tid & 7) * 8;

    wmma::fragment<wmma::accumulator, 16, 16, 16, float> acc[2][2];
#pragma unroll
    for (int i = 0; i < 2; i++)
#pragma unroll
        for (int j = 0; j < 2; j++) wmma::fill_fragment(acc[i][j], 0.f);

    uint4 pa[2];
    float4 pb0, pb1;
#pragma unroll
    for (int l = 0; l < 2; l++)
        pa[l] = *(const uint4*)&A[(size_t)(rowBase + aRow[l]) * K + aK[l]];
    pb0 = *(const float4*)&B[(size_t)bRow * Nn + bCol];
    pb1 = *(const float4*)&B[(size_t)bRow * Nn + bCol + 4];

    for (int k0 = 0; k0 < K; k0 += 32) {
#pragma unroll
        for (int l = 0; l < 2; l++)
            *(uint4*)&As[aRow[l] * LDA2 + aK[l]] = pa[l];
        {
            __half2 h0 = __floats2half2_rn(pb0.x, pb0.y);
            __half2 h1 = __floats2half2_rn(pb0.z, pb0.w);
            __half2 h2 = __floats2half2_rn(pb1.x, pb1.y);
            __half2 h3 = __floats2half2_rn(pb1.z, pb1.w);
            *(uint4*)&Bs[bRow * LDB2 + bCol] =
                make_uint4(*(unsigned*)&h0, *(unsigned*)&h1, *(unsigned*)&h2, *(unsigned*)&h3);
        }
        __syncthreads();

        if (k0 + 32 < K) {
#pragma unroll
            for (int l = 0; l < 2; l++)
                pa[l] = *(const uint4*)&A[(size_t)(rowBase + aRow[l]) * K + (k0 + 32) + aK[l]];
            pb0 = *(const float4*)&B[(size_t)(k0 + 32 + bRow) * Nn + bCol];
            pb1 = *(const float4*)&B[(size_t)(k0 + 32 + bRow) * Nn + bCol + 4];
        }

#pragma unroll
        for (int kk = 0; kk < 32; kk += 16) {
            wmma::fragment<wmma::matrix_a, 16, 16, 16, __half, wmma::row_major> af[2];
            wmma::fragment<wmma::matrix_b, 16, 16, 16, __half, wmma::row_major> bf[2];
#pragma unroll
            for (int i = 0; i < 2; i++)
                wmma::load_matrix_sync(af[i], &As[(wm + i * 16) * LDA2 + kk], LDA2);
#pragma unroll
            for (int j = 0; j < 2; j++)
                wmma::load_matrix_sync(bf[j], &Bs[kk * LDB2 + wn + j * 16], LDB2);
#pragma unroll
            for (int i = 0; i < 2; i++)
#pragma unroll
                for (int j = 0; j < 2; j++)
                    wmma::mma_sync(acc[i][j], af[i], bf[j], acc[i][j]);
        }
        __syncthreads();
    }

#pragma unroll
    for (int i = 0; i < 2; i++)
#pragma unroll
        for (int j = 0; j < 2; j++)
            wmma::store_matrix_sync(&sbuf[(wm + i * 16) * LDC + wn + j * 16], acc[i][j],
                                    LDC, wmma::mem_row_major);
    __syncthreads();

    const int row  = tid >> 1;
    const int half = tid & 1;
    const int gr   = rowBase + row;
    const float* crow = &sbuf[row * LDC + half * 32];
    const float* ap = av + half * 32;
    const float* rp = rv + half * 32;

    float el = 0.f, er = 0.f;
    unsigned w[16];
#pragma unroll
    for (int d = 0; d < 32; d += 2) {
        float c0 = crow[d], c1 = crow[d + 1];
        el += c0 * ap[d] + c1 * ap[d + 1];
        er += c0 * rp[d] + c1 * rp[d + 1];
        __half2 hh = __floats2half2_rn(c0, c1);
        w[d >> 1] = *(unsigned*)&hh;
    }
    float elf = el + __shfl_xor_sync(FULL, el, 1);
    float erf = er + __shfl_xor_sync(FULL, er, 1);
    if (gr < NN) {
        if (half == 0) { g_el2[gr] = elf; g_er2[gr] = erf; }
        uint4* d4 = (uint4*)&g_f2h[(size_t)gr * ODIM + half * 32];
        const uint4* s4 = (const uint4*)w;
        d4[0] = s4[0]; d4[1] = s4[1]; d4[2] = s4[2]; d4[3] = s4[3];
    }
}

// ---------------- layer-1 aggregation: warp/node, single pass, fp16 gather, 4x unroll --
__global__ void __launch_bounds__(256)
agg1(const float* __restrict__ b1) {
    int warp = (blockIdx.x * blockDim.x + threadIdx.x) >> 5;
    if (warp >= NN) return;
    const int lane = threadIdx.x & 31;
    const int node = warp;
    const int h4 = lane >> 2;
    const int beg = g_off[node], end = g_off[node + 1];

    const float er = g_er1[node * HEADS + h4];

    float acc[8];
#pragma unroll
    for (int j = 0; j < 8; j++) acc[j] = 0.f;
    float ssum = 0.f;

    int i = beg;
    for (; i + 4 <= end; i += 4) {
        int s0 = g_psrc[i], s1 = g_psrc[i + 1], s2 = g_psrc[i + 2], s3 = g_psrc[i + 3];
        float a0 = __expf(lrelu(g_el1[s0 * HEADS + h4] + er));
        float a1 = __expf(lrelu(g_el1[s1 * HEADS + h4] + er));
        float a2 = __expf(lrelu(g_el1[s2 * HEADS + h4] + er));
        float a3 = __expf(lrelu(g_el1[s3 * HEADS + h4] + er));
        uint4 u0 = *(const uint4*)&g_f1h[(size_t)s0 * F1DIM + lane * 8];
        uint4 u1 = *(const uint4*)&g_f1h[(size_t)s1 * F1DIM + lane * 8];
        uint4 u2 = *(const uint4*)&g_f1h[(size_t)s2 * F1DIM + lane * 8];
        uint4 u3 = *(const uint4*)&g_f1h[(size_t)s3 * F1DIM + lane * 8];
        ssum += (a0 + a1) + (a2 + a3);
        const __half2* p0 = (const __half2*)&u0;
        const __half2* p1 = (const __half2*)&u1;
        const __half2* p2 = (const __half2*)&u2;
        const __half2* p3 = (const __half2*)&u3;
#pragma unroll
        for (int j = 0; j < 4; j++) {
            float2 f0 = __half22float2(p0[j]);
            float2 f1 = __half22float2(p1[j]);
            float2 f2 = __half22float2(p2[j]);
            float2 f3 = __half22float2(p3[j]);
            acc[2*j + 0] += (a0 * f0.x + a1 * f1.x) + (a2 * f2.x + a3 * f3.x);
            acc[2*j + 1] += (a0 * f0.y + a1 * f1.y) + (a2 * f2.y + a3 * f3.y);
        }
    }
    for (; i < end; i++) {
        int s0 = g_psrc[i];
        float a0 = __expf(lrelu(g_el1[s0 * HEADS + h4] + er));
        uint4 u0 = *(const uint4*)&g_f1h[(size_t)s0 * F1DIM + lane * 8];
        ssum += a0;
        const __half2* p0 = (const __half2*)&u0;
#pragma unroll
        for (int j = 0; j < 4; j++) {
            float2 f0 = __half22float2(p0[j]);
            acc[2*j + 0] += a0 * f0.x;
            acc[2*j + 1] += a0 * f0.y;
        }
    }

    const float inv = ssum > 0.f ? 1.f / ssum : 0.f;
    const float4* bp = (const float4*)&b1[lane * 8];
    float4 bb0 = bp[0], bb1 = bp[1];
    float hv[8];
    hv[0] = acc[0] * inv + bb0.x; hv[1] = acc[1] * inv + bb0.y;
    hv[2] = acc[2] * inv + bb0.z; hv[3] = acc[3] * inv + bb0.w;
    hv[4] = acc[4] * inv + bb1.x; hv[5] = acc[5] * inv + bb1.y;
    hv[6] = acc[6] * inv + bb1.z; hv[7] = acc[7] * inv + bb1.w;
    unsigned w[4];
#pragma unroll
    for (int j = 0; j < 4; j++) {
        float x0 = hv[2*j],   e0 = x0 > 0.f ? x0 : expm1f(x0);
        float x1 = hv[2*j+1], e1 = x1 > 0.f ? x1 : expm1f(x1);
        __half2 hh = __floats2half2_rn(e0, e1);
        w[j] = *(unsigned*)&hh;
    }
    *(uint4*)&g_hh[(size_t)node * F1DIM + lane * 8] = *(const uint4*)w;
}

// ---------------- layer-2 aggregation: warp/node, single pass, fp16 gather ----------
__global__ void __launch_bounds__(256)
agg2(float* __restrict__ out, const float* __restrict__ b2) {
    int warp = (blockIdx.x * blockDim.x + threadIdx.x) >> 5;
    if (warp >= NN) return;
    const int lane = threadIdx.x & 31;
    const int node = warp;
    const int beg = g_off[node], end = g_off[node + 1];

    const float er = g_er2[node];

    float a0 = 0.f, a1 = 0.f, ssum = 0.f;
    int i = beg;
    for (; i + 4 <= end; i += 4) {
        int s0 = g_psrc[i], s1 = g_psrc[i+1], s2 = g_psrc[i+2], s3 = g_psrc[i+3];
        float e0 = __expf(lrelu(g_el2[s0] + er));
        float e1 = __expf(lrelu(g_el2[s1] + er));
        float e2 = __expf(lrelu(g_el2[s2] + er));
        float e3 = __expf(lrelu(g_el2[s3] + er));
        float2 v0 = __half22float2(*(const __half2*)&g_f2h[(size_t)s0 * ODIM + lane * 2]);
        float2 v1 = __half22float2(*(const __half2*)&g_f2h[(size_t)s1 * ODIM + lane * 2]);
        float2 v2 = __half22float2(*(const __half2*)&g_f2h[(size_t)s2 * ODIM + lane * 2]);
        float2 v3 = __half22float2(*(const __half2*)&g_f2h[(size_t)s3 * ODIM + lane * 2]);
        ssum += (e0 + e1) + (e2 + e3);
        a0 += e0 * v0.x + e1 * v1.x + e2 * v2.x + e3 * v3.x;
        a1 += e0 * v0.y + e1 * v1.y + e2 * v2.y + e3 * v3.y;
    }
    for (; i < end; i++) {
        int s = g_psrc[i];
        float e0 = __expf(lrelu(g_el2[s] + er));
        float2 v = __half22float2(*(const __half2*)&g_f2h[(size_t)s * ODIM + lane * 2]);
        ssum += e0;
        a0 += e0 * v.x;
        a1 += e0 * v.y;
    }
    const float inv = ssum > 0.f ? 1.f / ssum : 0.f;
    float2 bb = *(const float2*)&b2[lane * 2];
    *(float2*)&out[(size_t)node * ODIM + lane * 2] = make_float2(a0 * inv + bb.x, a1 * inv + bb.y);
}

// ---------------- launch ----------------
extern "C" void kernel_launch(void* const* d_in, const int* in_sizes, int n_in,
                              void* d_out, int out_size) {
    const float* feat = (const float*)d_in[0];
    const int*   src  = (const int*)  d_in[1];
    const int*   dst  = (const int*)  d_in[2];
    const float* W1   = (const float*)d_in[3];
    const float* al1  = (const float*)d_in[4];
    const float* ar1  = (const float*)d_in[5];
    const float* b1   = (const float*)d_in[6];
    const float* W2   = (const float*)d_in[7];
    const float* al2  = (const float*)d_in[8];
    const float* ar2  = (const float*)d_in[9];
    const float* b2   = (const float*)d_in[10];
    float* out = (float*)d_out;

    __half* phh;
    cudaGetSymbolAddress((void**)&phh, g_hh);

    const int T = 256;
    auto cdiv = [](long long a, long long b) { return (int)((a + b - 1) / b); };

    // CSR build (shared by both layers)
    zero_cnt<<<cdiv(NN, T), T>>>();
    count_dst<<<cdiv(NE, T), T>>>(dst);
    scan_off<<<1, 1024>>>();
    place_edges<<<cdiv(NE, T), T>>>(src, dst);

    // Layer 1: f1h/el1/er1 = fused(feat @ W1), fp16 MMA (A,B converted on load)
    gemm1_fused<<<dim3(F1DIM / 64, NNP / 128), 256>>>(feat, W1, al1, ar1, NN, IN_DIM, F1DIM);
    agg1<<<cdiv((long long)NN * 32, T), T>>>(b1);

    // Layer 2: f2h/el2/er2 = fused(g_hh @ W2), fp16 MMA; g_hh pad rows stay 0 -> safe
    gemm2_fused<<<dim3(1, NNP / 128), 256>>>(phh, W2, al2, ar2, F1DIM, ODIM);
    agg2<<<cdiv((long long)NN * 32, T), T>>>(out, b2);
}